// round 2
// baseline (speedup 1.0000x reference)
#include <cuda_runtime.h>
#include <cstddef>

// ---------------------------------------------------------------------------
// Problem constants
// ---------------------------------------------------------------------------
#define Bq   4
#define Tq   2048
#define Dq   1024
#define Hq   16
#define DHq  64
#define INNERq 1024
#define SCALEq 0.125f     // 64^-0.5

// ---------------------------------------------------------------------------
// Scratch (device globals; allocation is forbidden)
// ---------------------------------------------------------------------------
__device__ float g_Q[(size_t)Bq * Tq * INNERq];
__device__ float g_K[(size_t)Bq * Tq * INNERq];
__device__ float g_V[(size_t)Bq * Tq * INNERq];
__device__ float g_A[(size_t)Bq * Tq * INNERq];   // attention output [B,T,H*DH]

// ---------------------------------------------------------------------------
// SGEMM: C[M,N] = A[M,K] @ B[K,N] (+ bias[N])
// 128x128 block tile, BK=8, 8x8 per-thread microtile, 256 threads.
// ---------------------------------------------------------------------------
#define BM 128
#define BN 128
#define BK 8
#define TM 8
#define TN 8

__global__ __launch_bounds__(256) void sgemm_kernel(
    const float* __restrict__ A, const float* __restrict__ B,
    float* __restrict__ C, const float* __restrict__ bias,
    int M, int N, int K)
{
    __shared__ float As[BK * BM];
    __shared__ float Bs[BK * BN];

    const int tid = threadIdx.x;
    const int cRow = blockIdx.y;
    const int cCol = blockIdx.x;

    const int threadCol = tid % (BN / TN);   // 0..15
    const int threadRow = tid / (BN / TN);   // 0..15

    const int innerRowA = tid / (BK / 4);    // 0..127
    const int innerColA = tid % (BK / 4);    // 0..1
    const int innerRowB = tid / (BN / 4);    // 0..7
    const int innerColB = tid % (BN / 4);    // 0..31

    const float* Ab = A + (size_t)cRow * BM * K;
    const float* Bb = B + (size_t)cCol * BN;

    float acc[TM][TN];
#pragma unroll
    for (int i = 0; i < TM; ++i)
#pragma unroll
        for (int j = 0; j < TN; ++j) acc[i][j] = 0.0f;

    float regM[TM], regN[TN];

    for (int k0 = 0; k0 < K; k0 += BK) {
        float4 a4 = *reinterpret_cast<const float4*>(
            &Ab[(size_t)innerRowA * K + k0 + innerColA * 4]);
        As[(innerColA * 4 + 0) * BM + innerRowA] = a4.x;
        As[(innerColA * 4 + 1) * BM + innerRowA] = a4.y;
        As[(innerColA * 4 + 2) * BM + innerRowA] = a4.z;
        As[(innerColA * 4 + 3) * BM + innerRowA] = a4.w;

        float4 b4 = *reinterpret_cast<const float4*>(
            &Bb[(size_t)(k0 + innerRowB) * N + innerColB * 4]);
        *reinterpret_cast<float4*>(&Bs[innerRowB * BN + innerColB * 4]) = b4;

        __syncthreads();

#pragma unroll
        for (int k = 0; k < BK; ++k) {
#pragma unroll
            for (int i = 0; i < TM; ++i) regM[i] = As[k * BM + threadRow * TM + i];
#pragma unroll
            for (int j = 0; j < TN; ++j) regN[j] = Bs[k * BN + threadCol * TN + j];
#pragma unroll
            for (int i = 0; i < TM; ++i)
#pragma unroll
                for (int j = 0; j < TN; ++j)
                    acc[i][j] += regM[i] * regN[j];
        }
        __syncthreads();
    }

#pragma unroll
    for (int i = 0; i < TM; ++i) {
        const int row = cRow * BM + threadRow * TM + i;
#pragma unroll
        for (int j = 0; j < TN; j += 4) {
            const int col = cCol * BN + threadCol * TN + j;
            float4 v;
            v.x = acc[i][j + 0];
            v.y = acc[i][j + 1];
            v.z = acc[i][j + 2];
            v.w = acc[i][j + 3];
            if (bias) {
                v.x += bias[col + 0];
                v.y += bias[col + 1];
                v.z += bias[col + 2];
                v.w += bias[col + 3];
            }
            *reinterpret_cast<float4*>(&C[(size_t)row * N + col]) = v;
        }
    }
}

// ---------------------------------------------------------------------------
// Flash attention: per block = one (b, h, 64-query tile).
// 256 threads as 16x16 grid, each owns a 4x4 microtile of the 64x64 S/P/O.
// Online softmax; mask added before max; Q pre-scaled.
// ---------------------------------------------------------------------------
#define BQT 64
#define BKT 64
#define PADW 65   // 64+1: row stride 65 -> 2-way worst-case bank pattern

__global__ __launch_bounds__(256) void flash_kernel(
    const float* __restrict__ mask, // [B,1,T,T]
    float* __restrict__ Out)        // g_A  [B,T,H*DH]
{
    extern __shared__ float sm[];
    float* sQ = sm;                        // 64 x 65
    float* sK = sQ + BQT * PADW;           // 64 x 65
    float* sV = sK + BKT * PADW;           // 64 x 65
    float* sP = sV + BKT * PADW;           // 64 x 65

    const int tid = threadIdx.x;
    const int tx = tid & 15;   // column group
    const int ty = tid >> 4;   // row group
    const int q0 = blockIdx.x * BQT;
    const int h  = blockIdx.y;
    const int b  = blockIdx.z;

    const float* Qg = g_Q + (size_t)b * Tq * INNERq + (size_t)h * DHq;
    const float* Kg = g_K + (size_t)b * Tq * INNERq + (size_t)h * DHq;
    const float* Vg = g_V + (size_t)b * Tq * INNERq + (size_t)h * DHq;
    const float* Mg = mask + (size_t)b * Tq * Tq;

    // Load Q tile (pre-scaled)
    for (int idx = tid; idx < BQT * DHq; idx += 256) {
        const int r = idx >> 6, c = idx & 63;
        sQ[r * PADW + c] = Qg[(size_t)(q0 + r) * INNERq + c] * SCALEq;
    }

    float m_i[4], l_i[4], o[4][4];
#pragma unroll
    for (int i = 0; i < 4; ++i) {
        m_i[i] = -1e30f;
        l_i[i] = 0.0f;
#pragma unroll
        for (int j = 0; j < 4; ++j) o[i][j] = 0.0f;
    }

    for (int j0 = 0; j0 < Tq; j0 += BKT) {
        __syncthreads();  // protect sK/sV/sP from previous iteration's readers
        for (int idx = tid; idx < BKT * DHq; idx += 256) {
            const int r = idx >> 6, c = idx & 63;
            sK[r * PADW + c] = Kg[(size_t)(j0 + r) * INNERq + c];
            sV[r * PADW + c] = Vg[(size_t)(j0 + r) * INNERq + c];
        }
        __syncthreads();

        // S = (Q*scale) @ K^T   (4x4 per thread)
        float s[4][4];
#pragma unroll
        for (int i = 0; i < 4; ++i)
#pragma unroll
            for (int j = 0; j < 4; ++j) s[i][j] = 0.0f;

#pragma unroll 4
        for (int d = 0; d < DHq; ++d) {
            float qr[4], kc[4];
#pragma unroll
            for (int i = 0; i < 4; ++i) qr[i] = sQ[(4 * ty + i) * PADW + d];
#pragma unroll
            for (int j = 0; j < 4; ++j) kc[j] = sK[(4 * tx + j) * PADW + d];
#pragma unroll
            for (int i = 0; i < 4; ++i)
#pragma unroll
                for (int j = 0; j < 4; ++j)
                    s[i][j] += qr[i] * kc[j];
        }

        // Add mask (before max — required for general masks)
#pragma unroll
        for (int i = 0; i < 4; ++i) {
            const float* mrow = Mg + (size_t)(q0 + 4 * ty + i) * Tq + j0 + 4 * tx;
#pragma unroll
            for (int j = 0; j < 4; ++j) s[i][j] += mrow[j];
        }

        // Online softmax per row (row spread across 16 tx lanes, same warp half)
#pragma unroll
        for (int i = 0; i < 4; ++i) {
            float mx = s[i][0];
#pragma unroll
            for (int j = 1; j < 4; ++j) mx = fmaxf(mx, s[i][j]);
#pragma unroll
            for (int off = 8; off > 0; off >>= 1)
                mx = fmaxf(mx, __shfl_xor_sync(0xffffffffu, mx, off, 16));

            const float m_new = fmaxf(m_i[i], mx);
            const float alpha = __expf(m_i[i] - m_new);

            float rs = 0.0f;
#pragma unroll
            for (int j = 0; j < 4; ++j) {
                s[i][j] = __expf(s[i][j] - m_new);
                rs += s[i][j];
            }
#pragma unroll
            for (int off = 8; off > 0; off >>= 1)
                rs += __shfl_xor_sync(0xffffffffu, rs, off, 16);

            l_i[i] = l_i[i] * alpha + rs;
            m_i[i] = m_new;
#pragma unroll
            for (int j = 0; j < 4; ++j) o[i][j] *= alpha;
#pragma unroll
            for (int j = 0; j < 4; ++j)
                sP[(4 * ty + i) * PADW + 4 * tx + j] = s[i][j];
        }
        __syncthreads();

        // O += P @ V
#pragma unroll 4
        for (int kk = 0; kk < BKT; ++kk) {
            float pr[4], vc[4];
#pragma unroll
            for (int i = 0; i < 4; ++i) pr[i] = sP[(4 * ty + i) * PADW + kk];
#pragma unroll
            for (int j = 0; j < 4; ++j) vc[j] = sV[kk * PADW + 4 * tx + j];
#pragma unroll
            for (int i = 0; i < 4; ++i)
#pragma unroll
                for (int j = 0; j < 4; ++j)
                    o[i][j] += pr[i] * vc[j];
        }
    }

    // Normalize + write to [B,T,H,DH] flat layout
#pragma unroll
    for (int i = 0; i < 4; ++i) {
        const float inv = 1.0f / l_i[i];
        float* orow = Out + (size_t)(b * Tq + q0 + 4 * ty + i) * INNERq
                          + (size_t)h * DHq + 4 * tx;
#pragma unroll
        for (int j = 0; j < 4; ++j) orow[j] = o[i][j] * inv;
    }
}

// ---------------------------------------------------------------------------
// kernel_launch
// Inputs (metadata order): x, attention_mask, Wq, Wk, Wv, Wo, bo
// ---------------------------------------------------------------------------
extern "C" void kernel_launch(void* const* d_in, const int* in_sizes, int n_in,
                              void* d_out, int out_size)
{
    (void)in_sizes; (void)n_in; (void)out_size;
    const float* x    = (const float*)d_in[0];
    const float* mask = (const float*)d_in[1];
    const float* Wq   = (const float*)d_in[2];
    const float* Wk   = (const float*)d_in[3];
    const float* Wv   = (const float*)d_in[4];
    const float* Wo   = (const float*)d_in[5];
    const float* bo   = (const float*)d_in[6];
    float* out = (float*)d_out;

    float *dQ, *dK, *dV, *dA;
    cudaGetSymbolAddress((void**)&dQ, g_Q);
    cudaGetSymbolAddress((void**)&dK, g_K);
    cudaGetSymbolAddress((void**)&dV, g_V);
    cudaGetSymbolAddress((void**)&dA, g_A);

    const int M = Bq * Tq;        // 8192
    const int N = INNERq;         // 1024
    const int K = Dq;             // 1024

    dim3 gGrid(N / BN, M / BM);   // (8, 64)
    dim3 gBlk(256);

    // Projections
    sgemm_kernel<<<gGrid, gBlk>>>(x, Wq, dQ, nullptr, M, N, K);
    sgemm_kernel<<<gGrid, gBlk>>>(x, Wk, dK, nullptr, M, N, K);
    sgemm_kernel<<<gGrid, gBlk>>>(x, Wv, dV, nullptr, M, N, K);

    // Flash attention
    const int smemBytes = 4 * BQT * PADW * (int)sizeof(float);  // 66560
    cudaFuncSetAttribute(flash_kernel,
                         cudaFuncAttributeMaxDynamicSharedMemorySize, smemBytes);
    dim3 fGrid(Tq / BQT, Hq, Bq);  // (32, 16, 4)
    flash_kernel<<<fGrid, gBlk, smemBytes>>>(mask, dA);

    // Output projection + bias
    sgemm_kernel<<<gGrid, gBlk>>>(dA, Wo, out, bo, M, Dq, INNERq);
}

// round 4
// speedup vs baseline: 1.3320x; 1.3320x over previous
#include <cuda_runtime.h>
#include <cuda_bf16.h>
#include <cstdint>
#include <cstddef>

// ---------------------------------------------------------------------------
// Problem constants
// ---------------------------------------------------------------------------
#define Bq   4
#define Tq   2048
#define Dq   1024
#define Hq   16
#define DHq  64
#define INNERq 1024
#define SCALEq 0.125f     // 64^-0.5

// ---------------------------------------------------------------------------
// Scratch (device globals; allocation is forbidden)
// ---------------------------------------------------------------------------
__device__ float g_Q[(size_t)Bq * Tq * INNERq];
__device__ float g_K[(size_t)Bq * Tq * INNERq];
__device__ float g_V[(size_t)Bq * Tq * INNERq];
__device__ float g_A[(size_t)Bq * Tq * INNERq];   // attention output [B,T,H*DH]

// bf16 split operands
__device__ __nv_bfloat16 s_xh[(size_t)Bq * Tq * Dq];
__device__ __nv_bfloat16 s_xl[(size_t)Bq * Tq * Dq];
__device__ __nv_bfloat16 s_ah[(size_t)Bq * Tq * INNERq];
__device__ __nv_bfloat16 s_al[(size_t)Bq * Tq * INNERq];
// transposed weights: Wt[n][k] = W[k][n]
__device__ __nv_bfloat16 s_wqh[(size_t)Dq * INNERq];
__device__ __nv_bfloat16 s_wql[(size_t)Dq * INNERq];
__device__ __nv_bfloat16 s_wkh[(size_t)Dq * INNERq];
__device__ __nv_bfloat16 s_wkl[(size_t)Dq * INNERq];
__device__ __nv_bfloat16 s_wvh[(size_t)Dq * INNERq];
__device__ __nv_bfloat16 s_wvl[(size_t)Dq * INNERq];
__device__ __nv_bfloat16 s_woh[(size_t)Dq * INNERq];
__device__ __nv_bfloat16 s_wol[(size_t)Dq * INNERq];

// ---------------------------------------------------------------------------
// PTX helpers (arch-agnostic: mma.sync / ldmatrix / cp.async only)
// ---------------------------------------------------------------------------
__device__ __forceinline__ uint32_t smem_u32(const void* p) {
    uint32_t a;
    asm("{ .reg .u64 t; cvta.to.shared.u64 t, %1; cvt.u32.u64 %0, t; }" : "=r"(a) : "l"(p));
    return a;
}

#define CP_ASYNC16(s, g) \
    asm volatile("cp.async.cg.shared.global [%0], [%1], 16;" :: "r"(s), "l"(g))
#define CP_COMMIT() asm volatile("cp.async.commit_group;" ::: "memory")
#define CP_WAIT0()  asm volatile("cp.async.wait_group 0;" ::: "memory")
#define CP_WAIT1()  asm volatile("cp.async.wait_group 1;" ::: "memory")

#define LDSM_X4(r0, r1, r2, r3, addr) \
    asm volatile("ldmatrix.sync.aligned.m8n8.x4.shared.b16 {%0,%1,%2,%3}, [%4];" \
                 : "=r"(r0), "=r"(r1), "=r"(r2), "=r"(r3) : "r"(addr))

#define MMA_BF16(c0, c1, c2, c3, a0, a1, a2, a3, b0, b1) \
    asm volatile("mma.sync.aligned.m16n8k16.row.col.f32.bf16.bf16.f32 " \
                 "{%0,%1,%2,%3}, {%4,%5,%6,%7}, {%8,%9}, {%0,%1,%2,%3};" \
                 : "+f"(c0), "+f"(c1), "+f"(c2), "+f"(c3) \
                 : "r"(a0), "r"(a1), "r"(a2), "r"(a3), "r"(b0), "r"(b1))

// ---------------------------------------------------------------------------
// fp32 -> bf16 hi/lo split (elementwise)
// ---------------------------------------------------------------------------
__global__ __launch_bounds__(256) void split_kernel(
    const float* __restrict__ in, __nv_bfloat16* __restrict__ hi,
    __nv_bfloat16* __restrict__ lo, int n)
{
    int i = (blockIdx.x * 256 + threadIdx.x) * 4;
    if (i >= n) return;
    float4 v = *reinterpret_cast<const float4*>(in + i);
    __nv_bfloat16 h0 = __float2bfloat16(v.x);
    __nv_bfloat16 h1 = __float2bfloat16(v.y);
    __nv_bfloat16 h2 = __float2bfloat16(v.z);
    __nv_bfloat16 h3 = __float2bfloat16(v.w);
    __nv_bfloat162 H0; H0.x = h0; H0.y = h1;
    __nv_bfloat162 H1; H1.x = h2; H1.y = h3;
    *reinterpret_cast<__nv_bfloat162*>(hi + i)     = H0;
    *reinterpret_cast<__nv_bfloat162*>(hi + i + 2) = H1;
    __nv_bfloat162 L0, L1;
    L0.x = __float2bfloat16(v.x - __bfloat162float(h0));
    L0.y = __float2bfloat16(v.y - __bfloat162float(h1));
    L1.x = __float2bfloat16(v.z - __bfloat162float(h2));
    L1.y = __float2bfloat16(v.w - __bfloat162float(h3));
    *reinterpret_cast<__nv_bfloat162*>(lo + i)     = L0;
    *reinterpret_cast<__nv_bfloat162*>(lo + i + 2) = L1;
}

// ---------------------------------------------------------------------------
// W[K,N] fp32 -> Wt[N,K] bf16 hi/lo (transpose + split)
// ---------------------------------------------------------------------------
__global__ __launch_bounds__(256) void tsplit_kernel(
    const float* __restrict__ W, __nv_bfloat16* __restrict__ th,
    __nv_bfloat16* __restrict__ tl, int K, int N)
{
    __shared__ float t[32][33];
    const int tx = threadIdx.x, ty = threadIdx.y;
    const int bx = blockIdx.x, by = blockIdx.y;
#pragma unroll
    for (int j = 0; j < 32; j += 8)
        t[ty + j][tx] = W[(size_t)(by * 32 + ty + j) * N + bx * 32 + tx];
    __syncthreads();
#pragma unroll
    for (int j = 0; j < 32; j += 8) {
        float v = t[tx][ty + j];
        const int n = bx * 32 + ty + j;
        const int k = by * 32 + tx;
        __nv_bfloat16 h = __float2bfloat16(v);
        th[(size_t)n * K + k] = h;
        tl[(size_t)n * K + k] = __float2bfloat16(v - __bfloat162float(h));
    }
}

// ---------------------------------------------------------------------------
// mma.sync bf16 split GEMM: C[M,N] = (Ah+Al)[M,K] @ (Bh+Bl)^T, B given [N,K].
// 128x128 CTA tile, BK=32, double-buffered cp.async, 8 warps (4m x 2n),
// warp tile 32x64 = 2x8 m16n8k16 tiles. 3 passes: Ah*Bh + Ah*Bl + Al*Bh.
// ---------------------------------------------------------------------------
#define GBM 128
#define GBN 128
#define GBK 32
#define PADH 40          // padded row length in halves (80 bytes)
#define TILEB (128 * PADH * 2)           // 10240 bytes per tile
#define STAGEB (4 * TILEB)               // Ah, Al, Bh, Bl
#define GEMM_SMEM (2 * STAGEB)           // 81920 bytes

__global__ __launch_bounds__(256, 2) void gemm_mma_kernel(
    const __nv_bfloat16* __restrict__ Ah, const __nv_bfloat16* __restrict__ Al,
    const __nv_bfloat16* __restrict__ Bh, const __nv_bfloat16* __restrict__ Bl,
    float* __restrict__ C, const float* __restrict__ bias, int M, int N, int K)
{
    extern __shared__ char smem[];
    const uint32_t sb = smem_u32(smem);

    const int tid = threadIdx.x;
    const int wid = tid >> 5;
    const int lane = tid & 31;
    const int warp_m = wid >> 1;          // 0..3
    const int warp_n = wid & 1;           // 0..1
    const int row0 = blockIdx.y * GBM;
    const int col0 = blockIdx.x * GBN;

    // per-thread load mapping: 512 16B-chunks per tile -> 2 per thread
    const int r0l = (tid * 2) >> 2;       // row of first chunk
    const int c0l = (tid * 2) & 3;        // 16B segment of first chunk (0..3)
    const int r1l = (tid * 2 + 1) >> 2;
    const int c1l = (tid * 2 + 1) & 3;

    float acc[2][8][4];
#pragma unroll
    for (int i = 0; i < 2; ++i)
#pragma unroll
        for (int j = 0; j < 8; ++j)
#pragma unroll
            for (int q = 0; q < 4; ++q) acc[i][j][q] = 0.0f;

    auto load_stage = [&](int stage, int k0) {
        const uint32_t st = sb + stage * STAGEB;
        const __nv_bfloat16* gA[2] = { Ah, Al };
        const __nv_bfloat16* gB[2] = { Bh, Bl };
#pragma unroll
        for (int half = 0; half < 2; ++half) {
            // A tile
            {
                const uint32_t s0 = st + half * TILEB + r0l * 80 + c0l * 16;
                const uint32_t s1 = st + half * TILEB + r1l * 80 + c1l * 16;
                const __nv_bfloat16* g0 = gA[half] + (size_t)(row0 + r0l) * K + k0 + c0l * 8;
                const __nv_bfloat16* g1 = gA[half] + (size_t)(row0 + r1l) * K + k0 + c1l * 8;
                CP_ASYNC16(s0, g0);
                CP_ASYNC16(s1, g1);
            }
            // B tile
            {
                const uint32_t s0 = st + (2 + half) * TILEB + r0l * 80 + c0l * 16;
                const uint32_t s1 = st + (2 + half) * TILEB + r1l * 80 + c1l * 16;
                const __nv_bfloat16* g0 = gB[half] + (size_t)(col0 + r0l) * K + k0 + c0l * 8;
                const __nv_bfloat16* g1 = gB[half] + (size_t)(col0 + r1l) * K + k0 + c1l * 8;
                CP_ASYNC16(s0, g0);
                CP_ASYNC16(s1, g1);
            }
        }
    };

    load_stage(0, 0);
    CP_COMMIT();

    const int chunks = K / GBK;
    for (int c = 0; c < chunks; ++c) {
        if (c + 1 < chunks) {
            load_stage((c + 1) & 1, (c + 1) * GBK);
            CP_COMMIT();
            CP_WAIT1();
        } else {
            CP_WAIT0();
        }
        __syncthreads();

        const uint32_t st = sb + (c & 1) * STAGEB;
        const uint32_t aH = st;
        const uint32_t aL = st + TILEB;
        const uint32_t bH = st + 2 * TILEB;
        const uint32_t bL = st + 3 * TILEB;

#pragma unroll
        for (int kst = 0; kst < 2; ++kst) {
            const int kb = kst * 32 + (lane >> 4) * 16;   // byte offset within row

            // A fragments (hi & lo), 2 m-tiles each
            uint32_t ah[2][4], al[2][4];
#pragma unroll
            for (int mt = 0; mt < 2; ++mt) {
                const int arow = warp_m * 32 + mt * 16 + (lane & 15);
                LDSM_X4(ah[mt][0], ah[mt][1], ah[mt][2], ah[mt][3], aH + arow * 80 + kb);
                LDSM_X4(al[mt][0], al[mt][1], al[mt][2], al[mt][3], aL + arow * 80 + kb);
            }

            // B in two groups of 4 n-tiles to bound registers
#pragma unroll
            for (int g = 0; g < 2; ++g) {
                uint32_t bh[4][2], bl[4][2];
                const int brow_in = (lane & 7) + ((lane >> 4) << 3);
                const int bkb = kst * 32 + ((lane >> 3) & 1) * 16;
#pragma unroll
                for (int p = 0; p < 2; ++p) {   // each x4 covers 2 n-tiles
                    const int nb = warp_n * 64 + g * 32 + p * 16;
                    const uint32_t ba = (nb + brow_in) * 80 + bkb;
                    LDSM_X4(bh[2 * p][0], bh[2 * p][1], bh[2 * p + 1][0], bh[2 * p + 1][1],
                            bH + ba);
                    LDSM_X4(bl[2 * p][0], bl[2 * p][1], bl[2 * p + 1][0], bl[2 * p + 1][1],
                            bL + ba);
                }
#pragma unroll
                for (int mt = 0; mt < 2; ++mt)
#pragma unroll
                    for (int nt = 0; nt < 4; ++nt) {
                        float* cc = acc[mt][g * 4 + nt];
                        // Ah*Bh
                        MMA_BF16(cc[0], cc[1], cc[2], cc[3],
                                 ah[mt][0], ah[mt][1], ah[mt][2], ah[mt][3],
                                 bh[nt][0], bh[nt][1]);
                        // Ah*Bl
                        MMA_BF16(cc[0], cc[1], cc[2], cc[3],
                                 ah[mt][0], ah[mt][1], ah[mt][2], ah[mt][3],
                                 bl[nt][0], bl[nt][1]);
                        // Al*Bh
                        MMA_BF16(cc[0], cc[1], cc[2], cc[3],
                                 al[mt][0], al[mt][1], al[mt][2], al[mt][3],
                                 bh[nt][0], bh[nt][1]);
                    }
            }
        }
        __syncthreads();
    }

    // epilogue
#pragma unroll
    for (int mt = 0; mt < 2; ++mt) {
        const int rbase = row0 + warp_m * 32 + mt * 16 + (lane >> 2);
#pragma unroll
        for (int nt = 0; nt < 8; ++nt) {
            const int cbase = col0 + warp_n * 64 + nt * 8 + (lane & 3) * 2;
            float2 v0, v1;
            v0.x = acc[mt][nt][0]; v0.y = acc[mt][nt][1];
            v1.x = acc[mt][nt][2]; v1.y = acc[mt][nt][3];
            if (bias) {
                const float b0 = bias[cbase], b1 = bias[cbase + 1];
                v0.x += b0; v0.y += b1;
                v1.x += b0; v1.y += b1;
            }
            *reinterpret_cast<float2*>(C + (size_t)rbase * N + cbase) = v0;
            *reinterpret_cast<float2*>(C + (size_t)(rbase + 8) * N + cbase) = v1;
        }
    }
}

// ---------------------------------------------------------------------------
// Flash attention (fp32 SIMT, unchanged)
// ---------------------------------------------------------------------------
#define BQT 64
#define BKT 64
#define PADW 65

__global__ __launch_bounds__(256) void flash_kernel(
    const float* __restrict__ mask, float* __restrict__ Out)
{
    extern __shared__ float sm[];
    float* sQ = sm;
    float* sK = sQ + BQT * PADW;
    float* sV = sK + BKT * PADW;
    float* sP = sV + BKT * PADW;

    const int tid = threadIdx.x;
    const int tx = tid & 15;
    const int ty = tid >> 4;
    const int q0 = blockIdx.x * BQT;
    const int h  = blockIdx.y;
    const int b  = blockIdx.z;

    const float* Qg = g_Q + (size_t)b * Tq * INNERq + (size_t)h * DHq;
    const float* Kg = g_K + (size_t)b * Tq * INNERq + (size_t)h * DHq;
    const float* Vg = g_V + (size_t)b * Tq * INNERq + (size_t)h * DHq;
    const float* Mg = mask + (size_t)b * Tq * Tq;

    for (int idx = tid; idx < BQT * DHq; idx += 256) {
        const int r = idx >> 6, c = idx & 63;
        sQ[r * PADW + c] = Qg[(size_t)(q0 + r) * INNERq + c] * SCALEq;
    }

    float m_i[4], l_i[4], o[4][4];
#pragma unroll
    for (int i = 0; i < 4; ++i) {
        m_i[i] = -1e30f;
        l_i[i] = 0.0f;
#pragma unroll
        for (int j = 0; j < 4; ++j) o[i][j] = 0.0f;
    }

    for (int j0 = 0; j0 < Tq; j0 += BKT) {
        __syncthreads();
        for (int idx = tid; idx < BKT * DHq; idx += 256) {
            const int r = idx >> 6, c = idx & 63;
            sK[r * PADW + c] = Kg[(size_t)(j0 + r) * INNERq + c];
            sV[r * PADW + c] = Vg[(size_t)(j0 + r) * INNERq + c];
        }
        __syncthreads();

        float s[4][4];
#pragma unroll
        for (int i = 0; i < 4; ++i)
#pragma unroll
            for (int j = 0; j < 4; ++j) s[i][j] = 0.0f;

#pragma unroll 4
        for (int d = 0; d < DHq; ++d) {
            float qr[4], kc[4];
#pragma unroll
            for (int i = 0; i < 4; ++i) qr[i] = sQ[(4 * ty + i) * PADW + d];
#pragma unroll
            for (int j = 0; j < 4; ++j) kc[j] = sK[(4 * tx + j) * PADW + d];
#pragma unroll
            for (int i = 0; i < 4; ++i)
#pragma unroll
                for (int j = 0; j < 4; ++j)
                    s[i][j] += qr[i] * kc[j];
        }

#pragma unroll
        for (int i = 0; i < 4; ++i) {
            const float* mrow = Mg + (size_t)(q0 + 4 * ty + i) * Tq + j0 + 4 * tx;
#pragma unroll
            for (int j = 0; j < 4; ++j) s[i][j] += mrow[j];
        }

#pragma unroll
        for (int i = 0; i < 4; ++i) {
            float mx = s[i][0];
#pragma unroll
            for (int j = 1; j < 4; ++j) mx = fmaxf(mx, s[i][j]);
#pragma unroll
            for (int off = 8; off > 0; off >>= 1)
                mx = fmaxf(mx, __shfl_xor_sync(0xffffffffu, mx, off, 16));

            const float m_new = fmaxf(m_i[i], mx);
            const float alpha = __expf(m_i[i] - m_new);

            float rs = 0.0f;
#pragma unroll
            for (int j = 0; j < 4; ++j) {
                s[i][j] = __expf(s[i][j] - m_new);
                rs += s[i][j];
            }
#pragma unroll
            for (int off = 8; off > 0; off >>= 1)
                rs += __shfl_xor_sync(0xffffffffu, rs, off, 16);

            l_i[i] = l_i[i] * alpha + rs;
            m_i[i] = m_new;
#pragma unroll
            for (int j = 0; j < 4; ++j) o[i][j] *= alpha;
#pragma unroll
            for (int j = 0; j < 4; ++j)
                sP[(4 * ty + i) * PADW + 4 * tx + j] = s[i][j];
        }
        __syncthreads();

#pragma unroll 4
        for (int kk = 0; kk < BKT; ++kk) {
            float pr[4], vc[4];
#pragma unroll
            for (int i = 0; i < 4; ++i) pr[i] = sP[(4 * ty + i) * PADW + kk];
#pragma unroll
            for (int j = 0; j < 4; ++j) vc[j] = sV[kk * PADW + 4 * tx + j];
#pragma unroll
            for (int i = 0; i < 4; ++i)
#pragma unroll
                for (int j = 0; j < 4; ++j)
                    o[i][j] += pr[i] * vc[j];
        }
    }

#pragma unroll
    for (int i = 0; i < 4; ++i) {
        const float inv = 1.0f / l_i[i];
        float* orow = Out + (size_t)(b * Tq + q0 + 4 * ty + i) * INNERq
                          + (size_t)h * DHq + 4 * tx;
#pragma unroll
        for (int j = 0; j < 4; ++j) orow[j] = o[i][j] * inv;
    }
}

// ---------------------------------------------------------------------------
// kernel_launch
// Inputs: x, attention_mask, Wq, Wk, Wv, Wo, bo
// ---------------------------------------------------------------------------
extern "C" void kernel_launch(void* const* d_in, const int* in_sizes, int n_in,
                              void* d_out, int out_size)
{
    (void)in_sizes; (void)n_in; (void)out_size;
    const float* x    = (const float*)d_in[0];
    const float* mask = (const float*)d_in[1];
    const float* Wq   = (const float*)d_in[2];
    const float* Wk   = (const float*)d_in[3];
    const float* Wv   = (const float*)d_in[4];
    const float* Wo   = (const float*)d_in[5];
    const float* bo   = (const float*)d_in[6];
    float* out = (float*)d_out;

    float *dQ, *dK, *dV, *dA;
    cudaGetSymbolAddress((void**)&dQ, g_Q);
    cudaGetSymbolAddress((void**)&dK, g_K);
    cudaGetSymbolAddress((void**)&dV, g_V);
    cudaGetSymbolAddress((void**)&dA, g_A);
    __nv_bfloat16 *xh, *xl, *ah, *al;
    cudaGetSymbolAddress((void**)&xh, s_xh);
    cudaGetSymbolAddress((void**)&xl, s_xl);
    cudaGetSymbolAddress((void**)&ah, s_ah);
    cudaGetSymbolAddress((void**)&al, s_al);
    __nv_bfloat16 *wqh, *wql, *wkh, *wkl, *wvh, *wvl, *woh, *wol;
    cudaGetSymbolAddress((void**)&wqh, s_wqh);
    cudaGetSymbolAddress((void**)&wql, s_wql);
    cudaGetSymbolAddress((void**)&wkh, s_wkh);
    cudaGetSymbolAddress((void**)&wkl, s_wkl);
    cudaGetSymbolAddress((void**)&wvh, s_wvh);
    cudaGetSymbolAddress((void**)&wvl, s_wvl);
    cudaGetSymbolAddress((void**)&woh, s_woh);
    cudaGetSymbolAddress((void**)&wol, s_wol);

    const int M = Bq * Tq;     // 8192
    const int N = INNERq;      // 1024
    const int K = Dq;          // 1024
    const int nx = M * K;      // 8388608

    // conversions
    split_kernel<<<nx / (256 * 4), 256>>>(x, xh, xl, nx);
    dim3 tGrid(N / 32, K / 32), tBlk(32, 8);
    tsplit_kernel<<<tGrid, tBlk>>>(Wq, wqh, wql, K, N);
    tsplit_kernel<<<tGrid, tBlk>>>(Wk, wkh, wkl, K, N);
    tsplit_kernel<<<tGrid, tBlk>>>(Wv, wvh, wvl, K, N);
    tsplit_kernel<<<tGrid, tBlk>>>(Wo, woh, wol, K, N);

    // projections (mma.sync bf16 split)
    cudaFuncSetAttribute(gemm_mma_kernel,
                         cudaFuncAttributeMaxDynamicSharedMemorySize, GEMM_SMEM);
    dim3 gGrid(N / GBN, M / GBM);   // (8, 64)
    gemm_mma_kernel<<<gGrid, 256, GEMM_SMEM>>>(xh, xl, wqh, wql, dQ, nullptr, M, N, K);
    gemm_mma_kernel<<<gGrid, 256, GEMM_SMEM>>>(xh, xl, wkh, wkl, dK, nullptr, M, N, K);
    gemm_mma_kernel<<<gGrid, 256, GEMM_SMEM>>>(xh, xl, wvh, wvl, dV, nullptr, M, N, K);

    // flash attention (fp32)
    const int smemBytes = 4 * BQT * PADW * (int)sizeof(float);
    cudaFuncSetAttribute(flash_kernel,
                         cudaFuncAttributeMaxDynamicSharedMemorySize, smemBytes);
    dim3 fGrid(Tq / BQT, Hq, Bq);
    flash_kernel<<<fGrid, 256, smemBytes>>>(mask, dA);

    // output projection
    split_kernel<<<nx / (256 * 4), 256>>>(dA, ah, al, nx);
    gemm_mma_kernel<<<gGrid, 256, GEMM_SMEM>>>(ah, al, woh, wol, out, bo, M, Dq, INNERq);
}

// round 5
// speedup vs baseline: 3.0895x; 2.3194x over previous
#include <cuda_runtime.h>
#include <cuda_bf16.h>
#include <cstdint>
#include <cstddef>

// ---------------------------------------------------------------------------
// Problem constants
// ---------------------------------------------------------------------------
#define Bq   4
#define Tq   2048
#define Dq   1024
#define Hq   16
#define DHq  64
#define INNERq 1024
#define SCALEq 0.125f     // 64^-0.5

// ---------------------------------------------------------------------------
// Scratch (device globals; allocation is forbidden)
// ---------------------------------------------------------------------------
// bf16 split activations
__device__ __nv_bfloat16 s_xh[(size_t)Bq * Tq * Dq];
__device__ __nv_bfloat16 s_xl[(size_t)Bq * Tq * Dq];
__device__ __nv_bfloat16 s_qh[(size_t)Bq * Tq * INNERq];
__device__ __nv_bfloat16 s_ql[(size_t)Bq * Tq * INNERq];
__device__ __nv_bfloat16 s_kh[(size_t)Bq * Tq * INNERq];
__device__ __nv_bfloat16 s_kl[(size_t)Bq * Tq * INNERq];
__device__ __nv_bfloat16 s_vh[(size_t)Bq * Tq * INNERq];
__device__ __nv_bfloat16 s_vl[(size_t)Bq * Tq * INNERq];
__device__ __nv_bfloat16 s_ah[(size_t)Bq * Tq * INNERq];
__device__ __nv_bfloat16 s_al[(size_t)Bq * Tq * INNERq];
// transposed weights: Wt[n][k] = W[k][n]
__device__ __nv_bfloat16 s_wqh[(size_t)Dq * INNERq];
__device__ __nv_bfloat16 s_wql[(size_t)Dq * INNERq];
__device__ __nv_bfloat16 s_wkh[(size_t)Dq * INNERq];
__device__ __nv_bfloat16 s_wkl[(size_t)Dq * INNERq];
__device__ __nv_bfloat16 s_wvh[(size_t)Dq * INNERq];
__device__ __nv_bfloat16 s_wvl[(size_t)Dq * INNERq];
__device__ __nv_bfloat16 s_woh[(size_t)Dq * INNERq];
__device__ __nv_bfloat16 s_wol[(size_t)Dq * INNERq];

// ---------------------------------------------------------------------------
// PTX helpers (arch-agnostic: mma.sync / ldmatrix / cp.async only)
// ---------------------------------------------------------------------------
__device__ __forceinline__ uint32_t smem_u32(const void* p) {
    uint32_t a;
    asm("{ .reg .u64 t; cvta.to.shared.u64 t, %1; cvt.u32.u64 %0, t; }" : "=r"(a) : "l"(p));
    return a;
}

#define CP_ASYNC16(s, g) \
    asm volatile("cp.async.cg.shared.global [%0], [%1], 16;" :: "r"(s), "l"(g))
#define CP_COMMIT() asm volatile("cp.async.commit_group;" ::: "memory")
#define CP_WAIT0()  asm volatile("cp.async.wait_group 0;" ::: "memory")
#define CP_WAIT1()  asm volatile("cp.async.wait_group 1;" ::: "memory")

#define LDSM_X4(r0, r1, r2, r3, addr) \
    asm volatile("ldmatrix.sync.aligned.m8n8.x4.shared.b16 {%0,%1,%2,%3}, [%4];" \
                 : "=r"(r0), "=r"(r1), "=r"(r2), "=r"(r3) : "r"(addr))

#define LDSM_X4_T(r0, r1, r2, r3, addr) \
    asm volatile("ldmatrix.sync.aligned.m8n8.x4.trans.shared.b16 {%0,%1,%2,%3}, [%4];" \
                 : "=r"(r0), "=r"(r1), "=r"(r2), "=r"(r3) : "r"(addr))

#define MMA_BF16(c0, c1, c2, c3, a0, a1, a2, a3, b0, b1) \
    asm volatile("mma.sync.aligned.m16n8k16.row.col.f32.bf16.bf16.f32 " \
                 "{%0,%1,%2,%3}, {%4,%5,%6,%7}, {%8,%9}, {%0,%1,%2,%3};" \
                 : "+f"(c0), "+f"(c1), "+f"(c2), "+f"(c3) \
                 : "r"(a0), "r"(a1), "r"(a2), "r"(a3), "r"(b0), "r"(b1))

// ---------------------------------------------------------------------------
// fp32 -> bf16 hi/lo split (elementwise)
// ---------------------------------------------------------------------------
__global__ __launch_bounds__(256) void split_kernel(
    const float* __restrict__ in, __nv_bfloat16* __restrict__ hi,
    __nv_bfloat16* __restrict__ lo, int n)
{
    int i = (blockIdx.x * 256 + threadIdx.x) * 4;
    if (i >= n) return;
    float4 v = *reinterpret_cast<const float4*>(in + i);
    __nv_bfloat16 h0 = __float2bfloat16(v.x);
    __nv_bfloat16 h1 = __float2bfloat16(v.y);
    __nv_bfloat16 h2 = __float2bfloat16(v.z);
    __nv_bfloat16 h3 = __float2bfloat16(v.w);
    __nv_bfloat162 H0; H0.x = h0; H0.y = h1;
    __nv_bfloat162 H1; H1.x = h2; H1.y = h3;
    *reinterpret_cast<__nv_bfloat162*>(hi + i)     = H0;
    *reinterpret_cast<__nv_bfloat162*>(hi + i + 2) = H1;
    __nv_bfloat162 L0, L1;
    L0.x = __float2bfloat16(v.x - __bfloat162float(h0));
    L0.y = __float2bfloat16(v.y - __bfloat162float(h1));
    L1.x = __float2bfloat16(v.z - __bfloat162float(h2));
    L1.y = __float2bfloat16(v.w - __bfloat162float(h3));
    *reinterpret_cast<__nv_bfloat162*>(lo + i)     = L0;
    *reinterpret_cast<__nv_bfloat162*>(lo + i + 2) = L1;
}

// ---------------------------------------------------------------------------
// W[K,N] fp32 -> Wt[N,K] bf16 hi/lo (transpose + split)
// ---------------------------------------------------------------------------
__global__ __launch_bounds__(256) void tsplit_kernel(
    const float* __restrict__ W, __nv_bfloat16* __restrict__ th,
    __nv_bfloat16* __restrict__ tl, int K, int N)
{
    __shared__ float t[32][33];
    const int tx = threadIdx.x, ty = threadIdx.y;
    const int bx = blockIdx.x, by = blockIdx.y;
#pragma unroll
    for (int j = 0; j < 32; j += 8)
        t[ty + j][tx] = W[(size_t)(by * 32 + ty + j) * N + bx * 32 + tx];
    __syncthreads();
#pragma unroll
    for (int j = 0; j < 32; j += 8) {
        float v = t[tx][ty + j];
        const int n = bx * 32 + ty + j;
        const int k = by * 32 + tx;
        __nv_bfloat16 h = __float2bfloat16(v);
        th[(size_t)n * K + k] = h;
        tl[(size_t)n * K + k] = __float2bfloat16(v - __bfloat162float(h));
    }
}

// ---------------------------------------------------------------------------
// mma.sync bf16 split GEMM: C = (Ah+Al)[M,K] @ (Bh+Bl)^T, B given [N,K].
// Output: either fp32 (+bias) or bf16 hi/lo split (scaled).
// ---------------------------------------------------------------------------
#define GBM 128
#define GBN 128
#define GBK 32
#define TILEB (128 * 40 * 2)             // 10240 bytes per tile (80B rows)
#define STAGEB (4 * TILEB)
#define GEMM_SMEM (2 * STAGEB)           // 81920 bytes

__global__ __launch_bounds__(256, 2) void gemm_mma_kernel(
    const __nv_bfloat16* __restrict__ Ah, const __nv_bfloat16* __restrict__ Al,
    const __nv_bfloat16* __restrict__ Bh, const __nv_bfloat16* __restrict__ Bl,
    float* __restrict__ C, const float* __restrict__ bias,
    __nv_bfloat16* __restrict__ outH, __nv_bfloat16* __restrict__ outL,
    float scale, int M, int N, int K)
{
    extern __shared__ char smem[];
    const uint32_t sb = smem_u32(smem);

    const int tid = threadIdx.x;
    const int wid = tid >> 5;
    const int lane = tid & 31;
    const int warp_m = wid >> 1;
    const int warp_n = wid & 1;
    const int row0 = blockIdx.y * GBM;
    const int col0 = blockIdx.x * GBN;

    const int r0l = (tid * 2) >> 2;
    const int c0l = (tid * 2) & 3;
    const int r1l = (tid * 2 + 1) >> 2;
    const int c1l = (tid * 2 + 1) & 3;

    float acc[2][8][4];
#pragma unroll
    for (int i = 0; i < 2; ++i)
#pragma unroll
        for (int j = 0; j < 8; ++j)
#pragma unroll
            for (int q = 0; q < 4; ++q) acc[i][j][q] = 0.0f;

    auto load_stage = [&](int stage, int k0) {
        const uint32_t st = sb + stage * STAGEB;
        const __nv_bfloat16* gA[2] = { Ah, Al };
        const __nv_bfloat16* gB[2] = { Bh, Bl };
#pragma unroll
        for (int half = 0; half < 2; ++half) {
            {
                const uint32_t s0 = st + half * TILEB + r0l * 80 + c0l * 16;
                const uint32_t s1 = st + half * TILEB + r1l * 80 + c1l * 16;
                CP_ASYNC16(s0, gA[half] + (size_t)(row0 + r0l) * K + k0 + c0l * 8);
                CP_ASYNC16(s1, gA[half] + (size_t)(row0 + r1l) * K + k0 + c1l * 8);
            }
            {
                const uint32_t s0 = st + (2 + half) * TILEB + r0l * 80 + c0l * 16;
                const uint32_t s1 = st + (2 + half) * TILEB + r1l * 80 + c1l * 16;
                CP_ASYNC16(s0, gB[half] + (size_t)(col0 + r0l) * K + k0 + c0l * 8);
                CP_ASYNC16(s1, gB[half] + (size_t)(col0 + r1l) * K + k0 + c1l * 8);
            }
        }
    };

    load_stage(0, 0);
    CP_COMMIT();

    const int chunks = K / GBK;
    for (int c = 0; c < chunks; ++c) {
        if (c + 1 < chunks) {
            load_stage((c + 1) & 1, (c + 1) * GBK);
            CP_COMMIT();
            CP_WAIT1();
        } else {
            CP_WAIT0();
        }
        __syncthreads();

        const uint32_t st = sb + (c & 1) * STAGEB;
        const uint32_t aH = st;
        const uint32_t aL = st + TILEB;
        const uint32_t bH = st + 2 * TILEB;
        const uint32_t bL = st + 3 * TILEB;

#pragma unroll
        for (int kst = 0; kst < 2; ++kst) {
            const int kb = kst * 32 + (lane >> 4) * 16;

            uint32_t ah[2][4], al[2][4];
#pragma unroll
            for (int mt = 0; mt < 2; ++mt) {
                const int arow = warp_m * 32 + mt * 16 + (lane & 15);
                LDSM_X4(ah[mt][0], ah[mt][1], ah[mt][2], ah[mt][3], aH + arow * 80 + kb);
                LDSM_X4(al[mt][0], al[mt][1], al[mt][2], al[mt][3], aL + arow * 80 + kb);
            }

#pragma unroll
            for (int g = 0; g < 2; ++g) {
                uint32_t bh[4][2], bl[4][2];
                const int brow_in = (lane & 7) + ((lane >> 4) << 3);
                const int bkb = kst * 32 + ((lane >> 3) & 1) * 16;
#pragma unroll
                for (int p = 0; p < 2; ++p) {
                    const int nb = warp_n * 64 + g * 32 + p * 16;
                    const uint32_t ba = (nb + brow_in) * 80 + bkb;
                    LDSM_X4(bh[2 * p][0], bh[2 * p][1], bh[2 * p + 1][0], bh[2 * p + 1][1],
                            bH + ba);
                    LDSM_X4(bl[2 * p][0], bl[2 * p][1], bl[2 * p + 1][0], bl[2 * p + 1][1],
                            bL + ba);
                }
#pragma unroll
                for (int mt = 0; mt < 2; ++mt)
#pragma unroll
                    for (int nt = 0; nt < 4; ++nt) {
                        float* cc = acc[mt][g * 4 + nt];
                        MMA_BF16(cc[0], cc[1], cc[2], cc[3],
                                 ah[mt][0], ah[mt][1], ah[mt][2], ah[mt][3],
                                 bh[nt][0], bh[nt][1]);
                        MMA_BF16(cc[0], cc[1], cc[2], cc[3],
                                 ah[mt][0], ah[mt][1], ah[mt][2], ah[mt][3],
                                 bl[nt][0], bl[nt][1]);
                        MMA_BF16(cc[0], cc[1], cc[2], cc[3],
                                 al[mt][0], al[mt][1], al[mt][2], al[mt][3],
                                 bh[nt][0], bh[nt][1]);
                    }
            }
        }
        __syncthreads();
    }

    // epilogue
#pragma unroll
    for (int mt = 0; mt < 2; ++mt) {
        const int rbase = row0 + warp_m * 32 + mt * 16 + (lane >> 2);
#pragma unroll
        for (int nt = 0; nt < 8; ++nt) {
            const int cbase = col0 + warp_n * 64 + nt * 8 + (lane & 3) * 2;
            float v0 = acc[mt][nt][0], v1 = acc[mt][nt][1];
            float v2 = acc[mt][nt][2], v3 = acc[mt][nt][3];
            if (outH) {
                v0 *= scale; v1 *= scale; v2 *= scale; v3 *= scale;
                __nv_bfloat162 h01 = __float22bfloat162_rn(make_float2(v0, v1));
                __nv_bfloat162 h23 = __float22bfloat162_rn(make_float2(v2, v3));
                float2 f01 = __bfloat1622float2(h01);
                float2 f23 = __bfloat1622float2(h23);
                __nv_bfloat162 l01 = __float22bfloat162_rn(make_float2(v0 - f01.x, v1 - f01.y));
                __nv_bfloat162 l23 = __float22bfloat162_rn(make_float2(v2 - f23.x, v3 - f23.y));
                *reinterpret_cast<__nv_bfloat162*>(outH + (size_t)rbase * N + cbase) = h01;
                *reinterpret_cast<__nv_bfloat162*>(outH + (size_t)(rbase + 8) * N + cbase) = h23;
                *reinterpret_cast<__nv_bfloat162*>(outL + (size_t)rbase * N + cbase) = l01;
                *reinterpret_cast<__nv_bfloat162*>(outL + (size_t)(rbase + 8) * N + cbase) = l23;
            } else {
                if (bias) {
                    const float b0 = bias[cbase], b1 = bias[cbase + 1];
                    v0 += b0; v1 += b1; v2 += b0; v3 += b1;
                }
                float2 w0 = make_float2(v0, v1), w1 = make_float2(v2, v3);
                *reinterpret_cast<float2*>(C + (size_t)rbase * N + cbase) = w0;
                *reinterpret_cast<float2*>(C + (size_t)(rbase + 8) * N + cbase) = w1;
            }
        }
    }
}

// ---------------------------------------------------------------------------
// Tensor-core flash attention (bf16 split, mma.sync).
// Block: (b, h, 128-query tile). 8 warps, each owns 16 query rows.
// KV chunks of 64, cp.async double-buffered. P kept in registers.
// ---------------------------------------------------------------------------
#define FBQ 128
#define FBK 64
#define FROWB 144                         // 72 halves per row (padded)
#define FQ_TILE (FBQ * FROWB)             // 18432 B
#define FKV_TILE (FBK * FROWB)            // 9216 B
#define F_QH 0
#define F_QL FQ_TILE
#define F_ST (2 * FQ_TILE)                // 36864
#define F_STAGE (4 * FKV_TILE)            // 36864
#define FLASH_SMEM (F_ST + 2 * F_STAGE)   // 110592 B

__global__ __launch_bounds__(256, 2) void flash_mma_kernel(
    const float* __restrict__ mask,
    const __nv_bfloat16* __restrict__ Qh, const __nv_bfloat16* __restrict__ Ql,
    const __nv_bfloat16* __restrict__ Kh, const __nv_bfloat16* __restrict__ Kl,
    const __nv_bfloat16* __restrict__ Vh, const __nv_bfloat16* __restrict__ Vl,
    __nv_bfloat16* __restrict__ Oh, __nv_bfloat16* __restrict__ Ol)
{
    extern __shared__ char smem[];
    const uint32_t sb = smem_u32(smem);

    const int tid  = threadIdx.x;
    const int wid  = tid >> 5;
    const int lane = tid & 31;
    const int q0 = blockIdx.x * FBQ;
    const int h  = blockIdx.y;
    const int b  = blockIdx.z;

    const size_t headoff = (size_t)b * Tq * INNERq + (size_t)h * DHq;
    const __nv_bfloat16* gQh = Qh + headoff;
    const __nv_bfloat16* gQl = Ql + headoff;
    const __nv_bfloat16* gKh = Kh + headoff;
    const __nv_bfloat16* gKl = Kl + headoff;
    const __nv_bfloat16* gVh = Vh + headoff;
    const __nv_bfloat16* gVl = Vl + headoff;
    const float* Mg = mask + (size_t)b * Tq * Tq;

    // ---- prologue: Q tiles (hi/lo) + KV stage 0 via cp.async ----
    {
        // Q: 2 tiles x 128 rows x 8 segs = 2048 chunks
#pragma unroll
        for (int t = 0; t < 8; ++t) {
            const int id = t * 256 + tid;
            const int tile = id >> 10;          // 0=hi, 1=lo
            const int rem = id & 1023;
            const int row = rem >> 3;
            const int seg = rem & 7;
            const uint32_t s = sb + tile * FQ_TILE + row * FROWB + seg * 16;
            const __nv_bfloat16* g = (tile ? gQl : gQh) + (size_t)(q0 + row) * INNERq + seg * 8;
            CP_ASYNC16(s, g);
        }
        // KV stage 0
#pragma unroll
        for (int t = 0; t < 8; ++t) {
            const int id = t * 256 + tid;
            const int tile = id >> 9;           // 0=Kh,1=Kl,2=Vh,3=Vl
            const int rem = id & 511;
            const int row = rem >> 3;
            const int seg = rem & 7;
            const uint32_t s = sb + F_ST + tile * FKV_TILE + row * FROWB + seg * 16;
            const __nv_bfloat16* base = (tile == 0) ? gKh : (tile == 1) ? gKl
                                       : (tile == 2) ? gVh : gVl;
            CP_ASYNC16(s, base + (size_t)row * INNERq + seg * 8);
        }
        CP_COMMIT();
    }

    float o[8][4];
#pragma unroll
    for (int t = 0; t < 8; ++t)
#pragma unroll
        for (int j = 0; j < 4; ++j) o[t][j] = 0.0f;
    float m0 = -1e30f, m1 = -1e30f, l0 = 0.0f, l1 = 0.0f;

    const int r0g = q0 + wid * 16 + (lane >> 2);   // this thread's global row (low)
    const int quadcol = (lane & 3) * 2;

    const int chunks = Tq / FBK;   // 32
    for (int c = 0; c < chunks; ++c) {
        const int j0 = c * FBK;
        if (c + 1 < chunks) {
            const int jn = j0 + FBK;
            const uint32_t stn = sb + F_ST + ((c + 1) & 1) * F_STAGE;
#pragma unroll
            for (int t = 0; t < 8; ++t) {
                const int id = t * 256 + tid;
                const int tile = id >> 9;
                const int rem = id & 511;
                const int row = rem >> 3;
                const int seg = rem & 7;
                const uint32_t s = stn + tile * FKV_TILE + row * FROWB + seg * 16;
                const __nv_bfloat16* base = (tile == 0) ? gKh : (tile == 1) ? gKl
                                           : (tile == 2) ? gVh : gVl;
                CP_ASYNC16(s, base + (size_t)(jn + row) * INNERq + seg * 8);
            }
            CP_COMMIT();
            CP_WAIT1();
        } else {
            CP_WAIT0();
        }
        __syncthreads();

        const uint32_t st = sb + F_ST + (c & 1) * F_STAGE;
        const uint32_t kH = st;
        const uint32_t kL = st + FKV_TILE;
        const uint32_t vH = st + 2 * FKV_TILE;
        const uint32_t vL = st + 3 * FKV_TILE;

        // ---- S = Q K^T (split, 3 passes) ----
        float s[8][4];
#pragma unroll
        for (int t = 0; t < 8; ++t)
#pragma unroll
            for (int j = 0; j < 4; ++j) s[t][j] = 0.0f;

        const int brow_in = (lane & 7) + ((lane >> 4) << 3);
#pragma unroll
        for (int kk = 0; kk < 4; ++kk) {
            uint32_t qh4[4], ql4[4];
            const uint32_t qa = sb + (wid * 16 + (lane & 15)) * FROWB
                              + kk * 32 + (lane >> 4) * 16;
            LDSM_X4(qh4[0], qh4[1], qh4[2], qh4[3], qa);
            LDSM_X4(ql4[0], ql4[1], ql4[2], ql4[3], qa + FQ_TILE);

            const int bkb = kk * 32 + ((lane >> 3) & 1) * 16;
#pragma unroll
            for (int p = 0; p < 4; ++p) {
                uint32_t bh[2][2], bl[2][2];
                const uint32_t ba = (p * 16 + brow_in) * FROWB + bkb;
                LDSM_X4(bh[0][0], bh[0][1], bh[1][0], bh[1][1], kH + ba);
                LDSM_X4(bl[0][0], bl[0][1], bl[1][0], bl[1][1], kL + ba);
#pragma unroll
                for (int u = 0; u < 2; ++u) {
                    float* cc = s[2 * p + u];
                    MMA_BF16(cc[0], cc[1], cc[2], cc[3],
                             qh4[0], qh4[1], qh4[2], qh4[3], bh[u][0], bh[u][1]);
                    MMA_BF16(cc[0], cc[1], cc[2], cc[3],
                             ql4[0], ql4[1], ql4[2], ql4[3], bh[u][0], bh[u][1]);
                    MMA_BF16(cc[0], cc[1], cc[2], cc[3],
                             qh4[0], qh4[1], qh4[2], qh4[3], bl[u][0], bl[u][1]);
                }
            }
        }

        // ---- mask + online softmax ----
        const float* m0p = Mg + (size_t)r0g * Tq + j0 + quadcol;
        const float* m1p = m0p + 8 * Tq;
#pragma unroll
        for (int t = 0; t < 8; ++t) {
            float2 mv0 = *reinterpret_cast<const float2*>(m0p + t * 8);
            float2 mv1 = *reinterpret_cast<const float2*>(m1p + t * 8);
            s[t][0] += mv0.x; s[t][1] += mv0.y;
            s[t][2] += mv1.x; s[t][3] += mv1.y;
        }

        float mx0 = -1e30f, mx1 = -1e30f;
#pragma unroll
        for (int t = 0; t < 8; ++t) {
            mx0 = fmaxf(mx0, fmaxf(s[t][0], s[t][1]));
            mx1 = fmaxf(mx1, fmaxf(s[t][2], s[t][3]));
        }
        mx0 = fmaxf(mx0, __shfl_xor_sync(0xffffffffu, mx0, 1));
        mx0 = fmaxf(mx0, __shfl_xor_sync(0xffffffffu, mx0, 2));
        mx1 = fmaxf(mx1, __shfl_xor_sync(0xffffffffu, mx1, 1));
        mx1 = fmaxf(mx1, __shfl_xor_sync(0xffffffffu, mx1, 2));

        const float mn0 = fmaxf(m0, mx0);
        const float mn1 = fmaxf(m1, mx1);
        const float a0 = __expf(m0 - mn0);
        const float a1 = __expf(m1 - mn1);
        m0 = mn0; m1 = mn1;

        float sum0 = 0.0f, sum1 = 0.0f;
#pragma unroll
        for (int t = 0; t < 8; ++t) {
            s[t][0] = __expf(s[t][0] - mn0);
            s[t][1] = __expf(s[t][1] - mn0);
            s[t][2] = __expf(s[t][2] - mn1);
            s[t][3] = __expf(s[t][3] - mn1);
            sum0 += s[t][0] + s[t][1];
            sum1 += s[t][2] + s[t][3];
        }
        sum0 += __shfl_xor_sync(0xffffffffu, sum0, 1);
        sum0 += __shfl_xor_sync(0xffffffffu, sum0, 2);
        sum1 += __shfl_xor_sync(0xffffffffu, sum1, 1);
        sum1 += __shfl_xor_sync(0xffffffffu, sum1, 2);
        l0 = l0 * a0 + sum0;
        l1 = l1 * a1 + sum1;

#pragma unroll
        for (int t = 0; t < 8; ++t) {
            o[t][0] *= a0; o[t][1] *= a0;
            o[t][2] *= a1; o[t][3] *= a1;
        }

        // ---- P fragments (hi/lo) from S registers ----
        uint32_t pH[4][4], pL[4][4];
#pragma unroll
        for (int j = 0; j < 4; ++j) {
#pragma unroll
            for (int u = 0; u < 2; ++u) {      // u=0: rows low (c0,c1), u=1: rows high (c2,c3)
#pragma unroll
                for (int w = 0; w < 2; ++w) {  // w: which S n-tile (2j / 2j+1)
                    const float e0 = s[2 * j + w][2 * u + 0];
                    const float e1 = s[2 * j + w][2 * u + 1];
                    __nv_bfloat162 hh = __float22bfloat162_rn(make_float2(e0, e1));
                    float2 hf = __bfloat1622float2(hh);
                    __nv_bfloat162 ll = __float22bfloat162_rn(
                        make_float2(e0 - hf.x, e1 - hf.y));
                    // A-frag order: a0=rows low k-low, a1=rows high k-low,
                    //               a2=rows low k-high, a3=rows high k-high
                    pH[j][2 * w + u] = *reinterpret_cast<uint32_t*>(&hh);
                    pL[j][2 * w + u] = *reinterpret_cast<uint32_t*>(&ll);
                }
            }
        }

        // ---- O += P V (split, 3 passes) ----
#pragma unroll
        for (int j = 0; j < 4; ++j) {
#pragma unroll
            for (int p = 0; p < 4; ++p) {
                uint32_t vh4[2][2], vl4[2][2];
                const uint32_t va = (j * 16 + (lane & 15)) * FROWB
                                  + p * 32 + (lane >> 4) * 16;
                LDSM_X4_T(vh4[0][0], vh4[0][1], vh4[1][0], vh4[1][1], vH + va);
                LDSM_X4_T(vl4[0][0], vl4[0][1], vl4[1][0], vl4[1][1], vL + va);
#pragma unroll
                for (int u = 0; u < 2; ++u) {
                    float* cc = o[2 * p + u];
                    MMA_BF16(cc[0], cc[1], cc[2], cc[3],
                             pH[j][0], pH[j][1], pH[j][2], pH[j][3],
                             vh4[u][0], vh4[u][1]);
                    MMA_BF16(cc[0], cc[1], cc[2], cc[3],
                             pL[j][0], pL[j][1], pL[j][2], pL[j][3],
                             vh4[u][0], vh4[u][1]);
                    MMA_BF16(cc[0], cc[1], cc[2], cc[3],
                             pH[j][0], pH[j][1], pH[j][2], pH[j][3],
                             vl4[u][0], vl4[u][1]);
                }
            }
        }
        __syncthreads();
    }

    // ---- epilogue: normalize, split to bf16 hi/lo, store ----
    const float inv0 = 1.0f / l0;
    const float inv1 = 1.0f / l1;
    const size_t row0o = ((size_t)b * Tq + r0g) * INNERq + (size_t)h * DHq;
    const size_t row1o = row0o + 8 * INNERq;
#pragma unroll
    for (int t = 0; t < 8; ++t) {
        const int col = t * 8 + quadcol;
        float v0 = o[t][0] * inv0, v1 = o[t][1] * inv0;
        float v2 = o[t][2] * inv1, v3 = o[t][3] * inv1;
        __nv_bfloat162 h01 = __float22bfloat162_rn(make_float2(v0, v1));
        __nv_bfloat162 h23 = __float22bfloat162_rn(make_float2(v2, v3));
        float2 f01 = __bfloat1622float2(h01);
        float2 f23 = __bfloat1622float2(h23);
        __nv_bfloat162 l01 = __float22bfloat162_rn(make_float2(v0 - f01.x, v1 - f01.y));
        __nv_bfloat162 l23 = __float22bfloat162_rn(make_float2(v2 - f23.x, v3 - f23.y));
        *reinterpret_cast<__nv_bfloat162*>(Oh + row0o + col) = h01;
        *reinterpret_cast<__nv_bfloat162*>(Ol + row0o + col) = l01;
        *reinterpret_cast<__nv_bfloat162*>(Oh + row1o + col) = h23;
        *reinterpret_cast<__nv_bfloat162*>(Ol + row1o + col) = l23;
    }
}

// ---------------------------------------------------------------------------
// kernel_launch
// Inputs: x, attention_mask, Wq, Wk, Wv, Wo, bo
// ---------------------------------------------------------------------------
extern "C" void kernel_launch(void* const* d_in, const int* in_sizes, int n_in,
                              void* d_out, int out_size)
{
    (void)in_sizes; (void)n_in; (void)out_size;
    const float* x    = (const float*)d_in[0];
    const float* mask = (const float*)d_in[1];
    const float* Wq   = (const float*)d_in[2];
    const float* Wk   = (const float*)d_in[3];
    const float* Wv   = (const float*)d_in[4];
    const float* Wo   = (const float*)d_in[5];
    const float* bo   = (const float*)d_in[6];
    float* out = (float*)d_out;

    __nv_bfloat16 *xh, *xl, *ah, *al;
    __nv_bfloat16 *qh, *ql, *kh, *kl, *vh, *vl;
    cudaGetSymbolAddress((void**)&xh, s_xh);
    cudaGetSymbolAddress((void**)&xl, s_xl);
    cudaGetSymbolAddress((void**)&ah, s_ah);
    cudaGetSymbolAddress((void**)&al, s_al);
    cudaGetSymbolAddress((void**)&qh, s_qh);
    cudaGetSymbolAddress((void**)&ql, s_ql);
    cudaGetSymbolAddress((void**)&kh, s_kh);
    cudaGetSymbolAddress((void**)&kl, s_kl);
    cudaGetSymbolAddress((void**)&vh, s_vh);
    cudaGetSymbolAddress((void**)&vl, s_vl);
    __nv_bfloat16 *wqh, *wql, *wkh, *wkl, *wvh, *wvl, *woh, *wol;
    cudaGetSymbolAddress((void**)&wqh, s_wqh);
    cudaGetSymbolAddress((void**)&wql, s_wql);
    cudaGetSymbolAddress((void**)&wkh, s_wkh);
    cudaGetSymbolAddress((void**)&wkl, s_wkl);
    cudaGetSymbolAddress((void**)&wvh, s_wvh);
    cudaGetSymbolAddress((void**)&wvl, s_wvl);
    cudaGetSymbolAddress((void**)&woh, s_woh);
    cudaGetSymbolAddress((void**)&wol, s_wol);

    const int M = Bq * Tq;     // 8192
    const int N = INNERq;      // 1024
    const int K = Dq;          // 1024
    const int nx = M * K;

    // conversions
    split_kernel<<<nx / (256 * 4), 256>>>(x, xh, xl, nx);
    dim3 tGrid(N / 32, K / 32), tBlk(32, 8);
    tsplit_kernel<<<tGrid, tBlk>>>(Wq, wqh, wql, K, N);
    tsplit_kernel<<<tGrid, tBlk>>>(Wk, wkh, wkl, K, N);
    tsplit_kernel<<<tGrid, tBlk>>>(Wv, wvh, wvl, K, N);
    tsplit_kernel<<<tGrid, tBlk>>>(Wo, woh, wol, K, N);

    // projections -> bf16 hi/lo (Q pre-scaled)
    cudaFuncSetAttribute(gemm_mma_kernel,
                         cudaFuncAttributeMaxDynamicSharedMemorySize, GEMM_SMEM);
    dim3 gGrid(N / GBN, M / GBM);
    gemm_mma_kernel<<<gGrid, 256, GEMM_SMEM>>>(xh, xl, wqh, wql,
        nullptr, nullptr, qh, ql, SCALEq, M, N, K);
    gemm_mma_kernel<<<gGrid, 256, GEMM_SMEM>>>(xh, xl, wkh, wkl,
        nullptr, nullptr, kh, kl, 1.0f, M, N, K);
    gemm_mma_kernel<<<gGrid, 256, GEMM_SMEM>>>(xh, xl, wvh, wvl,
        nullptr, nullptr, vh, vl, 1.0f, M, N, K);

    // flash attention (tensor cores) -> bf16 hi/lo
    cudaFuncSetAttribute(flash_mma_kernel,
                         cudaFuncAttributeMaxDynamicSharedMemorySize, FLASH_SMEM);
    dim3 fGrid(Tq / FBQ, Hq, Bq);   // (16, 16, 4)
    flash_mma_kernel<<<fGrid, 256, FLASH_SMEM>>>(mask, qh, ql, kh, kl, vh, vl, ah, al);

    // output projection (fp32 + bias)
    gemm_mma_kernel<<<gGrid, 256, GEMM_SMEM>>>(ah, al, woh, wol,
        out, bo, nullptr, nullptr, 1.0f, M, Dq, INNERq);
}